// round 12
// baseline (speedup 1.0000x reference)
#include <cuda_runtime.h>
#include <math.h>
#include <stdint.h>

#define N_NODES 50000
#define N_EDGES 800000
#define NFEAT   256
#define NHID    64
#define NCLASS  40
#define LOGSM_OFF (N_NODES * NCLASS)

typedef unsigned long long ull;

// Scratch (static __device__ — no allocations allowed)
__device__ float g_A[N_NODES * NHID];      // x @ W1
__device__ float g_hacc[N_NODES * NHID];   // spmm1 accumulator
__device__ float g_B[N_NODES * NCLASS];    // relu(hacc+b1) @ W2
__device__ float g_lacc[N_NODES * NCLASS]; // spmm2 accumulator

// ---------------------------------------------------------------------------
// tf32 helpers
// ---------------------------------------------------------------------------
__device__ __forceinline__ uint32_t f2tf32(float f) {
    uint32_t r;
    asm("cvt.rna.tf32.f32 %0, %1;" : "=r"(r) : "f"(f));
    return r;
}
__device__ __forceinline__ void mma_tf32(float* d, const uint32_t* a,
                                         uint32_t b0, uint32_t b1) {
    asm volatile(
        "mma.sync.aligned.m16n8k8.row.col.f32.tf32.tf32.f32 "
        "{%0,%1,%2,%3}, {%4,%5,%6,%7}, {%8,%9}, {%0,%1,%2,%3};"
        : "+f"(d[0]), "+f"(d[1]), "+f"(d[2]), "+f"(d[3])
        : "r"(a[0]), "r"(a[1]), "r"(a[2]), "r"(a[3]), "r"(b0), "r"(b1));
}

// W1 smem tile: one K-half [128 k x 64 n] as float2(hi,lo), n-major.
// Stride KP=132 float2 => bank (8n + 2k) mod 32 conflict-free.
#define KP 132
#define G1_SMEM (64 * KP * 8)  // 67584 bytes

// ---------------------------------------------------------------------------
// GEMM1 via mma.sync tf32 split-precision: g_A = x @ W1.  (R10 version)
// Also zeroes g_hacc / g_lacc in the prologue.
// ---------------------------------------------------------------------------
__global__ __launch_bounds__(256) void gemm1_tc_kernel(const float* __restrict__ x,
                                                       const float* __restrict__ W1) {
    extern __shared__ __align__(16) float2 Wt[]; // [64][KP]

    // ---- fused accumulator zeroing (graph replays need this every call) ----
    {
        int idx = blockIdx.x * 256 + threadIdx.x;
        int nthr = gridDim.x * 256;
        float4 z = make_float4(0.f, 0.f, 0.f, 0.f);
        float4* h4 = (float4*)g_hacc;
        float4* l4 = (float4*)g_lacc;
        for (int i = idx; i < (N_NODES * NHID) / 4; i += nthr) h4[i] = z;
        for (int i = idx; i < (N_NODES * NCLASS) / 4; i += nthr) l4[i] = z;
    }

    int tid = threadIdx.x;
    int warp = tid >> 5, lane = tid & 31;
    int grp = lane >> 2;      // node row / B col group
    int tig = lane & 3;       // k index within group

    int node0 = blockIdx.x * 128 + warp * 16;
    int r0 = node0 + grp;
    int r1 = r0 + 8;
    int rr0 = (r0 < N_NODES) ? r0 : (N_NODES - 1);
    int rr1 = (r1 < N_NODES) ? r1 : (N_NODES - 1);

    float d[8][4];
#pragma unroll
    for (int nt = 0; nt < 8; nt++)
#pragma unroll
        for (int j = 0; j < 4; j++) d[nt][j] = 0.f;

    for (int h = 0; h < 2; h++) {
        __syncthreads();
        for (int i = tid; i < 128 * 64; i += 256) {
            int kl = i >> 6;
            int n  = i & 63;
            float w = W1[(h * 128 + kl) * NHID + n];
            float hi = __uint_as_float(f2tf32(w));
            float lo = __uint_as_float(f2tf32(w - hi));
            Wt[n * KP + kl] = make_float2(hi, lo);
        }
        __syncthreads();

        int kg0 = h * 128;
#pragma unroll 4
        for (int ks = 0; ks < 16; ks++) {
            int kc = kg0 + ks * 8 + tig;
            float a0 = __ldg(&x[rr0 * NFEAT + kc]);
            float a1 = __ldg(&x[rr1 * NFEAT + kc]);
            float a2 = __ldg(&x[rr0 * NFEAT + kc + 4]);
            float a3 = __ldg(&x[rr1 * NFEAT + kc + 4]);
            uint32_t ah[4], al[4];
            ah[0] = f2tf32(a0); al[0] = f2tf32(a0 - __uint_as_float(ah[0]));
            ah[1] = f2tf32(a1); al[1] = f2tf32(a1 - __uint_as_float(ah[1]));
            ah[2] = f2tf32(a2); al[2] = f2tf32(a2 - __uint_as_float(ah[2]));
            ah[3] = f2tf32(a3); al[3] = f2tf32(a3 - __uint_as_float(ah[3]));

            int kb = ks * 8 + tig;
#pragma unroll
            for (int nt = 0; nt < 8; nt++) {
                float2 p0 = Wt[(nt * 8 + grp) * KP + kb];
                float2 p1 = Wt[(nt * 8 + grp) * KP + kb + 4];
                uint32_t b0h = __float_as_uint(p0.x), b0l = __float_as_uint(p0.y);
                uint32_t b1h = __float_as_uint(p1.x), b1l = __float_as_uint(p1.y);
                mma_tf32(d[nt], ah, b0h, b1h);
                mma_tf32(d[nt], ah, b0l, b1l);
                mma_tf32(d[nt], al, b0h, b1h);
            }
        }
    }

#pragma unroll
    for (int nt = 0; nt < 8; nt++) {
        int c = nt * 8 + 2 * tig;
        if (r0 < N_NODES)
            *(float2*)(g_A + r0 * NHID + c) = make_float2(d[nt][0], d[nt][1]);
        if (r1 < N_NODES)
            *(float2*)(g_A + r1 * NHID + c) = make_float2(d[nt][2], d[nt][3]);
    }
}

// ---------------------------------------------------------------------------
// SpMM1: 8 threads/edge, each handles 2 ADJACENT float4 chunks of one row.
// Same RED count as before; half the threads, half the meta loads, 2x MLP.
// ---------------------------------------------------------------------------
__global__ void spmm1_kernel(const float* __restrict__ ew,
                             const int* __restrict__ esrc,
                             const int* __restrict__ edst) {
    int gid = blockIdx.x * blockDim.x + threadIdx.x;
    int e = gid >> 3;
    if (e >= N_EDGES) return;
    int q = (gid & 7) * 2;   // chunk pair: q, q+1

    int s = __ldg(&esrc[e]);
    int d = __ldg(&edst[e]);
    float w = __ldg(&ew[e]);

    const float4* A = (const float4*)g_A;
    float4 a0 = A[s * 16 + q];
    float4 a1 = A[s * 16 + q + 1];
    float4 m0 = make_float4(a0.x * w, a0.y * w, a0.z * w, a0.w * w);
    float4 m1 = make_float4(a1.x * w, a1.y * w, a1.z * w, a1.w * w);
    float4* dstp = (float4*)&g_hacc[d * NHID + q * 4];
    atomicAdd(dstp,     m0);
    atomicAdd(dstp + 1, m1);
}

// ---------------------------------------------------------------------------
// Layer2 via mma.sync tf32: g_B = relu(g_hacc + b1) @ W2.  (R10 version)
// ---------------------------------------------------------------------------
#define KP2 68
__global__ __launch_bounds__(256) void layer2_tc_kernel(const float* __restrict__ b1,
                                                        const float* __restrict__ W2) {
    __shared__ float2 W2t[NCLASS * KP2]; // 40*68*8 = 21760 B
    __shared__ float b1s[NHID];

    int tid = threadIdx.x;
    for (int i = tid; i < NHID * NCLASS; i += 256) {
        int k = i / NCLASS, n = i - k * NCLASS;
        float w = W2[i];
        float hi = __uint_as_float(f2tf32(w));
        float lo = __uint_as_float(f2tf32(w - hi));
        W2t[n * KP2 + k] = make_float2(hi, lo);
    }
    if (tid < NHID) b1s[tid] = b1[tid];
    __syncthreads();

    int warp = tid >> 5, lane = tid & 31;
    int grp = lane >> 2, tig = lane & 3;

    int node0 = blockIdx.x * 128 + warp * 16;
    int r0 = node0 + grp;
    int r1 = r0 + 8;
    int rr0 = (r0 < N_NODES) ? r0 : (N_NODES - 1);
    int rr1 = (r1 < N_NODES) ? r1 : (N_NODES - 1);

    float d[5][4];
#pragma unroll
    for (int nt = 0; nt < 5; nt++)
#pragma unroll
        for (int j = 0; j < 4; j++) d[nt][j] = 0.f;

#pragma unroll
    for (int ks = 0; ks < 8; ks++) {
        int kc = ks * 8 + tig;
        float a0 = fmaxf(g_hacc[rr0 * NHID + kc]     + b1s[kc],     0.f);
        float a1 = fmaxf(g_hacc[rr1 * NHID + kc]     + b1s[kc],     0.f);
        float a2 = fmaxf(g_hacc[rr0 * NHID + kc + 4] + b1s[kc + 4], 0.f);
        float a3 = fmaxf(g_hacc[rr1 * NHID + kc + 4] + b1s[kc + 4], 0.f);
        uint32_t ah[4], al[4];
        ah[0] = f2tf32(a0); al[0] = f2tf32(a0 - __uint_as_float(ah[0]));
        ah[1] = f2tf32(a1); al[1] = f2tf32(a1 - __uint_as_float(ah[1]));
        ah[2] = f2tf32(a2); al[2] = f2tf32(a2 - __uint_as_float(ah[2]));
        ah[3] = f2tf32(a3); al[3] = f2tf32(a3 - __uint_as_float(ah[3]));

#pragma unroll
        for (int nt = 0; nt < 5; nt++) {
            float2 p0 = W2t[(nt * 8 + grp) * KP2 + kc];
            float2 p1 = W2t[(nt * 8 + grp) * KP2 + kc + 4];
            uint32_t b0h = __float_as_uint(p0.x), b0l = __float_as_uint(p0.y);
            uint32_t b1h = __float_as_uint(p1.x), b1l = __float_as_uint(p1.y);
            mma_tf32(d[nt], ah, b0h, b1h);
            mma_tf32(d[nt], ah, b0l, b1l);
            mma_tf32(d[nt], al, b0h, b1h);
        }
    }

#pragma unroll
    for (int nt = 0; nt < 5; nt++) {
        int c = nt * 8 + 2 * tig;
        if (r0 < N_NODES)
            *(float2*)(g_B + r0 * NCLASS + c) = make_float2(d[nt][0], d[nt][1]);
        if (r1 < N_NODES)
            *(float2*)(g_B + r1 * NCLASS + c) = make_float2(d[nt][2], d[nt][3]);
    }
}

// ---------------------------------------------------------------------------
// SpMM2: 5 threads/edge, each handles 2 ADJACENT float4 chunks of one row.
// ---------------------------------------------------------------------------
__global__ void spmm2_kernel(const float* __restrict__ ew,
                             const int* __restrict__ esrc,
                             const int* __restrict__ edst) {
    int gid = blockIdx.x * blockDim.x + threadIdx.x;
    int e = gid / 5;
    if (e >= N_EDGES) return;
    int q = (gid - e * 5) * 2;   // chunk pair: q, q+1

    int s = __ldg(&esrc[e]);
    int d = __ldg(&edst[e]);
    float w = __ldg(&ew[e]);

    const float4* B = (const float4*)g_B;
    float4 a0 = B[s * 10 + q];
    float4 a1 = B[s * 10 + q + 1];
    float4 m0 = make_float4(a0.x * w, a0.y * w, a0.z * w, a0.w * w);
    float4 m1 = make_float4(a1.x * w, a1.y * w, a1.z * w, a1.w * w);
    float4* dstp = (float4*)&g_lacc[d * NCLASS + q * 4];
    atomicAdd(dstp,     m0);
    atomicAdd(dstp + 1, m1);
}

// ---------------------------------------------------------------------------
// Finalize: logits = g_lacc + b2; out[0:2M]=logits, out[2M:4M]=log_softmax
// ---------------------------------------------------------------------------
__global__ __launch_bounds__(128) void finalize_kernel(const float* __restrict__ b2,
                                                       float* __restrict__ out) {
    __shared__ float b2s[NCLASS];
    if (threadIdx.x < NCLASS) b2s[threadIdx.x] = b2[threadIdx.x];
    __syncthreads();

    int node = blockIdx.x * 128 + threadIdx.x;
    if (node >= N_NODES) return;

    float v[NCLASS];
    float mx = -INFINITY;
    const float4* lin = (const float4*)(g_lacc + node * NCLASS);
#pragma unroll
    for (int jj = 0; jj < 10; jj++) {
        float4 a = lin[jj];
        v[jj * 4 + 0] = a.x + b2s[jj * 4 + 0];
        v[jj * 4 + 1] = a.y + b2s[jj * 4 + 1];
        v[jj * 4 + 2] = a.z + b2s[jj * 4 + 2];
        v[jj * 4 + 3] = a.w + b2s[jj * 4 + 3];
    }
#pragma unroll
    for (int j = 0; j < NCLASS; j++) mx = fmaxf(mx, v[j]);
    float s = 0.f;
#pragma unroll
    for (int j = 0; j < NCLASS; j++) s += expf(v[j] - mx);
    float lse = mx + logf(s);

    float4* o1 = (float4*)(out + node * NCLASS);
    float4* o2 = (float4*)(out + LOGSM_OFF + node * NCLASS);
#pragma unroll
    for (int jj = 0; jj < 10; jj++) {
        float4 a = make_float4(v[jj * 4 + 0], v[jj * 4 + 1],
                               v[jj * 4 + 2], v[jj * 4 + 3]);
        o1[jj] = a;
        float4 b = make_float4(a.x - lse, a.y - lse, a.z - lse, a.w - lse);
        o2[jj] = b;
    }
}

// ---------------------------------------------------------------------------
extern "C" void kernel_launch(void* const* d_in, const int* in_sizes, int n_in,
                              void* d_out, int out_size) {
    const float* x   = (const float*)d_in[0];
    const float* W1  = (const float*)d_in[1];
    const float* b1  = (const float*)d_in[2];
    const float* W2  = (const float*)d_in[3];
    const float* b2  = (const float*)d_in[4];
    const float* ew  = (const float*)d_in[5];
    const int*  esrc = (const int*)d_in[6];
    const int*  edst = (const int*)d_in[7];
    float* out = (float*)d_out;

    cudaFuncSetAttribute(gemm1_tc_kernel,
                         cudaFuncAttributeMaxDynamicSharedMemorySize, G1_SMEM);

    // GEMM1 via tf32 mma.sync + fused accumulator zeroing (R10 config)
    {
        int nblk = (N_NODES + 127) / 128; // 391
        gemm1_tc_kernel<<<nblk, 256, G1_SMEM>>>(x, W1);
    }
    // SpMM1 (8 threads/edge, 2 adjacent vector REDs each)
    {
        int total = N_EDGES * 8; // 6.4M
        spmm1_kernel<<<(total + 255) / 256, 256>>>(ew, esrc, edst);
    }
    // ReLU + bias + GEMM2 via tf32 mma.sync
    {
        int nblk = (N_NODES + 127) / 128; // 391
        layer2_tc_kernel<<<nblk, 256>>>(b1, W2);
    }
    // SpMM2 (5 threads/edge, 2 adjacent vector REDs each)
    {
        int total = N_EDGES * 5; // 4M
        spmm2_kernel<<<(total + 255) / 256, 256>>>(ew, esrc, edst);
    }
    // bias + log_softmax + write both outputs
    finalize_kernel<<<(N_NODES + 127) / 128, 128>>>(b2, out);
}

// round 13
// speedup vs baseline: 1.1141x; 1.1141x over previous
#include <cuda_runtime.h>
#include <math.h>
#include <stdint.h>

#define N_NODES 50000
#define N_EDGES 800000
#define NFEAT   256
#define NHID    64
#define NCLASS  40
#define LOGSM_OFF (N_NODES * NCLASS)

typedef unsigned long long ull;

// Scratch (static __device__ — no allocations allowed)
__device__ float g_A[N_NODES * NHID];      // x @ W1
__device__ float g_hacc[N_NODES * NHID];   // spmm1 accumulator
__device__ float g_B[N_NODES * NCLASS];    // relu(hacc+b1) @ W2
__device__ float g_lacc[N_NODES * NCLASS]; // spmm2 accumulator

// ---------------------------------------------------------------------------
// tf32 helpers
// ---------------------------------------------------------------------------
__device__ __forceinline__ uint32_t f2tf32(float f) {
    uint32_t r;
    asm("cvt.rna.tf32.f32 %0, %1;" : "=r"(r) : "f"(f));
    return r;
}
__device__ __forceinline__ void mma_tf32(float* d, const uint32_t* a,
                                         uint32_t b0, uint32_t b1) {
    asm volatile(
        "mma.sync.aligned.m16n8k8.row.col.f32.tf32.tf32.f32 "
        "{%0,%1,%2,%3}, {%4,%5,%6,%7}, {%8,%9}, {%0,%1,%2,%3};"
        : "+f"(d[0]), "+f"(d[1]), "+f"(d[2]), "+f"(d[3])
        : "r"(a[0]), "r"(a[1]), "r"(a[2]), "r"(a[3]), "r"(b0), "r"(b1));
}

// W1 smem tile: one K-half [128 k x 64 n] as float2(hi,lo), n-major.
// Stride KP=132 float2 => bank (8n + 2k) mod 32 conflict-free.
#define KP 132
#define G1_SMEM (64 * KP * 8)  // 67584 bytes

// ---------------------------------------------------------------------------
// GEMM1 via mma.sync tf32, 2-pass split precision: g_A ≈ x_hi @ (W_hi + W_lo).
// W keeps full fp32 precision (hi+lo); x rounded to tf32 (rel err ~1e-4).
// Also zeroes g_hacc / g_lacc in the prologue.
// ---------------------------------------------------------------------------
__global__ __launch_bounds__(256) void gemm1_tc_kernel(const float* __restrict__ x,
                                                       const float* __restrict__ W1) {
    extern __shared__ __align__(16) float2 Wt[]; // [64][KP]

    // ---- fused accumulator zeroing (graph replays need this every call) ----
    {
        int idx = blockIdx.x * 256 + threadIdx.x;
        int nthr = gridDim.x * 256;
        float4 z = make_float4(0.f, 0.f, 0.f, 0.f);
        float4* h4 = (float4*)g_hacc;
        float4* l4 = (float4*)g_lacc;
        for (int i = idx; i < (N_NODES * NHID) / 4; i += nthr) h4[i] = z;
        for (int i = idx; i < (N_NODES * NCLASS) / 4; i += nthr) l4[i] = z;
    }

    int tid = threadIdx.x;
    int warp = tid >> 5, lane = tid & 31;
    int grp = lane >> 2;      // node row / B col group
    int tig = lane & 3;       // k index within group

    int node0 = blockIdx.x * 128 + warp * 16;
    int r0 = node0 + grp;
    int r1 = r0 + 8;
    int rr0 = (r0 < N_NODES) ? r0 : (N_NODES - 1);
    int rr1 = (r1 < N_NODES) ? r1 : (N_NODES - 1);

    float d[8][4];
#pragma unroll
    for (int nt = 0; nt < 8; nt++)
#pragma unroll
        for (int j = 0; j < 4; j++) d[nt][j] = 0.f;

    for (int h = 0; h < 2; h++) {
        __syncthreads();
        for (int i = tid; i < 128 * 64; i += 256) {
            int kl = i >> 6;
            int n  = i & 63;
            float w = W1[(h * 128 + kl) * NHID + n];
            float hi = __uint_as_float(f2tf32(w));
            float lo = __uint_as_float(f2tf32(w - hi));
            Wt[n * KP + kl] = make_float2(hi, lo);
        }
        __syncthreads();

        int kg0 = h * 128;
#pragma unroll 4
        for (int ks = 0; ks < 16; ks++) {
            int kc = kg0 + ks * 8 + tig;
            float a0 = __ldg(&x[rr0 * NFEAT + kc]);
            float a1 = __ldg(&x[rr1 * NFEAT + kc]);
            float a2 = __ldg(&x[rr0 * NFEAT + kc + 4]);
            float a3 = __ldg(&x[rr1 * NFEAT + kc + 4]);
            uint32_t ah[4];
            ah[0] = f2tf32(a0);
            ah[1] = f2tf32(a1);
            ah[2] = f2tf32(a2);
            ah[3] = f2tf32(a3);

            int kb = ks * 8 + tig;
#pragma unroll
            for (int nt = 0; nt < 8; nt++) {
                float2 p0 = Wt[(nt * 8 + grp) * KP + kb];
                float2 p1 = Wt[(nt * 8 + grp) * KP + kb + 4];
                uint32_t b0h = __float_as_uint(p0.x), b0l = __float_as_uint(p0.y);
                uint32_t b1h = __float_as_uint(p1.x), b1l = __float_as_uint(p1.y);
                mma_tf32(d[nt], ah, b0h, b1h);
                mma_tf32(d[nt], ah, b0l, b1l);
            }
        }
    }

#pragma unroll
    for (int nt = 0; nt < 8; nt++) {
        int c = nt * 8 + 2 * tig;
        if (r0 < N_NODES)
            *(float2*)(g_A + r0 * NHID + c) = make_float2(d[nt][0], d[nt][1]);
        if (r1 < N_NODES)
            *(float2*)(g_A + r1 * NHID + c) = make_float2(d[nt][2], d[nt][3]);
    }
}

// ---------------------------------------------------------------------------
// SpMM1: g_hacc[dst] += g_A[src] * w   (16 threads/edge, ONE float4 RED each)
// ---------------------------------------------------------------------------
__global__ void spmm1_kernel(const float* __restrict__ ew,
                             const int* __restrict__ esrc,
                             const int* __restrict__ edst) {
    int gid = blockIdx.x * blockDim.x + threadIdx.x;
    int e = gid >> 4;
    if (e >= N_EDGES) return;
    int q = gid & 15;

    int s = __ldg(&esrc[e]);
    int d = __ldg(&edst[e]);
    float w = __ldg(&ew[e]);

    float4 a = ((const float4*)g_A)[s * 16 + q];
    float4 m = make_float4(a.x * w, a.y * w, a.z * w, a.w * w);
    atomicAdd((float4*)&g_hacc[d * NHID + q * 4], m);
}

// ---------------------------------------------------------------------------
// Layer2 via mma.sync tf32 (3-pass, full precision): g_B = relu(g_hacc+b1)@W2
// ---------------------------------------------------------------------------
#define KP2 68
__global__ __launch_bounds__(256) void layer2_tc_kernel(const float* __restrict__ b1,
                                                        const float* __restrict__ W2) {
    __shared__ float2 W2t[NCLASS * KP2]; // 40*68*8 = 21760 B
    __shared__ float b1s[NHID];

    int tid = threadIdx.x;
    for (int i = tid; i < NHID * NCLASS; i += 256) {
        int k = i / NCLASS, n = i - k * NCLASS;
        float w = W2[i];
        float hi = __uint_as_float(f2tf32(w));
        float lo = __uint_as_float(f2tf32(w - hi));
        W2t[n * KP2 + k] = make_float2(hi, lo);
    }
    if (tid < NHID) b1s[tid] = b1[tid];
    __syncthreads();

    int warp = tid >> 5, lane = tid & 31;
    int grp = lane >> 2, tig = lane & 3;

    int node0 = blockIdx.x * 128 + warp * 16;
    int r0 = node0 + grp;
    int r1 = r0 + 8;
    int rr0 = (r0 < N_NODES) ? r0 : (N_NODES - 1);
    int rr1 = (r1 < N_NODES) ? r1 : (N_NODES - 1);

    float d[5][4];
#pragma unroll
    for (int nt = 0; nt < 5; nt++)
#pragma unroll
        for (int j = 0; j < 4; j++) d[nt][j] = 0.f;

#pragma unroll
    for (int ks = 0; ks < 8; ks++) {
        int kc = ks * 8 + tig;
        float a0 = fmaxf(g_hacc[rr0 * NHID + kc]     + b1s[kc],     0.f);
        float a1 = fmaxf(g_hacc[rr1 * NHID + kc]     + b1s[kc],     0.f);
        float a2 = fmaxf(g_hacc[rr0 * NHID + kc + 4] + b1s[kc + 4], 0.f);
        float a3 = fmaxf(g_hacc[rr1 * NHID + kc + 4] + b1s[kc + 4], 0.f);
        uint32_t ah[4], al[4];
        ah[0] = f2tf32(a0); al[0] = f2tf32(a0 - __uint_as_float(ah[0]));
        ah[1] = f2tf32(a1); al[1] = f2tf32(a1 - __uint_as_float(ah[1]));
        ah[2] = f2tf32(a2); al[2] = f2tf32(a2 - __uint_as_float(ah[2]));
        ah[3] = f2tf32(a3); al[3] = f2tf32(a3 - __uint_as_float(ah[3]));

#pragma unroll
        for (int nt = 0; nt < 5; nt++) {
            float2 p0 = W2t[(nt * 8 + grp) * KP2 + kc];
            float2 p1 = W2t[(nt * 8 + grp) * KP2 + kc + 4];
            uint32_t b0h = __float_as_uint(p0.x), b0l = __float_as_uint(p0.y);
            uint32_t b1h = __float_as_uint(p1.x), b1l = __float_as_uint(p1.y);
            mma_tf32(d[nt], ah, b0h, b1h);
            mma_tf32(d[nt], ah, b0l, b1l);
            mma_tf32(d[nt], al, b0h, b1h);
        }
    }

#pragma unroll
    for (int nt = 0; nt < 5; nt++) {
        int c = nt * 8 + 2 * tig;
        if (r0 < N_NODES)
            *(float2*)(g_B + r0 * NCLASS + c) = make_float2(d[nt][0], d[nt][1]);
        if (r1 < N_NODES)
            *(float2*)(g_B + r1 * NCLASS + c) = make_float2(d[nt][2], d[nt][3]);
    }
}

// ---------------------------------------------------------------------------
// SpMM2: g_lacc[dst] += g_B[src] * w   (10 threads/edge, ONE float4 RED each)
// ---------------------------------------------------------------------------
__global__ void spmm2_kernel(const float* __restrict__ ew,
                             const int* __restrict__ esrc,
                             const int* __restrict__ edst) {
    int gid = blockIdx.x * blockDim.x + threadIdx.x;
    int e = gid / 10;
    if (e >= N_EDGES) return;
    int q = gid - e * 10;

    int s = __ldg(&esrc[e]);
    int d = __ldg(&edst[e]);
    float w = __ldg(&ew[e]);

    float4 a = ((const float4*)g_B)[s * 10 + q];
    float4 m = make_float4(a.x * w, a.y * w, a.z * w, a.w * w);
    atomicAdd((float4*)&g_lacc[d * NCLASS + q * 4], m);
}

// ---------------------------------------------------------------------------
// Finalize: logits = g_lacc + b2; out[0:2M]=logits, out[2M:4M]=log_softmax
// ---------------------------------------------------------------------------
__global__ __launch_bounds__(128) void finalize_kernel(const float* __restrict__ b2,
                                                       float* __restrict__ out) {
    __shared__ float b2s[NCLASS];
    if (threadIdx.x < NCLASS) b2s[threadIdx.x] = b2[threadIdx.x];
    __syncthreads();

    int node = blockIdx.x * 128 + threadIdx.x;
    if (node >= N_NODES) return;

    float v[NCLASS];
    float mx = -INFINITY;
    const float4* lin = (const float4*)(g_lacc + node * NCLASS);
#pragma unroll
    for (int jj = 0; jj < 10; jj++) {
        float4 a = lin[jj];
        v[jj * 4 + 0] = a.x + b2s[jj * 4 + 0];
        v[jj * 4 + 1] = a.y + b2s[jj * 4 + 1];
        v[jj * 4 + 2] = a.z + b2s[jj * 4 + 2];
        v[jj * 4 + 3] = a.w + b2s[jj * 4 + 3];
    }
#pragma unroll
    for (int j = 0; j < NCLASS; j++) mx = fmaxf(mx, v[j]);
    float s = 0.f;
#pragma unroll
    for (int j = 0; j < NCLASS; j++) s += expf(v[j] - mx);
    float lse = mx + logf(s);

    float4* o1 = (float4*)(out + node * NCLASS);
    float4* o2 = (float4*)(out + LOGSM_OFF + node * NCLASS);
#pragma unroll
    for (int jj = 0; jj < 10; jj++) {
        float4 a = make_float4(v[jj * 4 + 0], v[jj * 4 + 1],
                               v[jj * 4 + 2], v[jj * 4 + 3]);
        o1[jj] = a;
        float4 b = make_float4(a.x - lse, a.y - lse, a.z - lse, a.w - lse);
        o2[jj] = b;
    }
}

// ---------------------------------------------------------------------------
extern "C" void kernel_launch(void* const* d_in, const int* in_sizes, int n_in,
                              void* d_out, int out_size) {
    const float* x   = (const float*)d_in[0];
    const float* W1  = (const float*)d_in[1];
    const float* b1  = (const float*)d_in[2];
    const float* W2  = (const float*)d_in[3];
    const float* b2  = (const float*)d_in[4];
    const float* ew  = (const float*)d_in[5];
    const int*  esrc = (const int*)d_in[6];
    const int*  edst = (const int*)d_in[7];
    float* out = (float*)d_out;

    cudaFuncSetAttribute(gemm1_tc_kernel,
                         cudaFuncAttributeMaxDynamicSharedMemorySize, G1_SMEM);

    // GEMM1 via tf32 mma.sync (2-pass) + fused accumulator zeroing
    {
        int nblk = (N_NODES + 127) / 128; // 391
        gemm1_tc_kernel<<<nblk, 256, G1_SMEM>>>(x, W1);
    }
    // SpMM1 (vector RED scatter, R10-optimal mapping)
    {
        int total = N_EDGES * 16; // 12.8M
        spmm1_kernel<<<(total + 255) / 256, 256>>>(ew, esrc, edst);
    }
    // ReLU + bias + GEMM2 via tf32 mma.sync (3-pass)
    {
        int nblk = (N_NODES + 127) / 128; // 391
        layer2_tc_kernel<<<nblk, 256>>>(b1, W2);
    }
    // SpMM2 (vector RED scatter, R10-optimal mapping)
    {
        int total = N_EDGES * 10; // 8M
        spmm2_kernel<<<(total + 255) / 256, 256>>>(ew, esrc, edst);
    }
    // bias + log_softmax + write both outputs
    finalize_kernel<<<(N_NODES + 127) / 128, 128>>>(b2, out);
}

// round 14
// speedup vs baseline: 1.1300x; 1.0142x over previous
#include <cuda_runtime.h>
#include <math.h>
#include <stdint.h>

#define N_NODES 50000
#define N_EDGES 800000
#define NFEAT   256
#define NHID    64
#define NCLASS  40
#define LOGSM_OFF (N_NODES * NCLASS)

typedef unsigned long long ull;

// Scratch (static __device__ — no allocations allowed)
__device__ float g_A[N_NODES * NHID];      // x @ W1
__device__ float g_hacc[N_NODES * NHID];   // spmm1 accumulator
__device__ float g_B[N_NODES * NCLASS];    // relu(hacc+b1) @ W2
__device__ float g_lacc[N_NODES * NCLASS]; // spmm2 accumulator

// ---------------------------------------------------------------------------
// tf32 helpers
// ---------------------------------------------------------------------------
__device__ __forceinline__ uint32_t f2tf32(float f) {
    uint32_t r;
    asm("cvt.rna.tf32.f32 %0, %1;" : "=r"(r) : "f"(f));
    return r;
}
__device__ __forceinline__ void mma_tf32(float* d, const uint32_t* a,
                                         uint32_t b0, uint32_t b1) {
    asm volatile(
        "mma.sync.aligned.m16n8k8.row.col.f32.tf32.tf32.f32 "
        "{%0,%1,%2,%3}, {%4,%5,%6,%7}, {%8,%9}, {%0,%1,%2,%3};"
        : "+f"(d[0]), "+f"(d[1]), "+f"(d[2]), "+f"(d[3])
        : "r"(a[0]), "r"(a[1]), "r"(a[2]), "r"(a[3]), "r"(b0), "r"(b1));
}

// W1 smem tile: one K-half [128 k x 64 n] as float2(hi,lo), n-major.
// Stride KP=132 float2 => bank (8n + 2k) mod 32 conflict-free.
#define KP 132
#define G1_SMEM (64 * KP * 8)  // 67584 bytes

// ---------------------------------------------------------------------------
// GEMM1 via mma.sync tf32, 3-pass split precision (R10): g_A = x @ W1.
// Also zeroes g_hacc / g_lacc in the prologue.
// ---------------------------------------------------------------------------
__global__ __launch_bounds__(256) void gemm1_tc_kernel(const float* __restrict__ x,
                                                       const float* __restrict__ W1) {
    extern __shared__ __align__(16) float2 Wt[]; // [64][KP]

    // ---- fused accumulator zeroing (graph replays need this every call) ----
    {
        int idx = blockIdx.x * 256 + threadIdx.x;
        int nthr = gridDim.x * 256;
        float4 z = make_float4(0.f, 0.f, 0.f, 0.f);
        float4* h4 = (float4*)g_hacc;
        float4* l4 = (float4*)g_lacc;
        for (int i = idx; i < (N_NODES * NHID) / 4; i += nthr) h4[i] = z;
        for (int i = idx; i < (N_NODES * NCLASS) / 4; i += nthr) l4[i] = z;
    }

    int tid = threadIdx.x;
    int warp = tid >> 5, lane = tid & 31;
    int grp = lane >> 2;      // node row / B col group
    int tig = lane & 3;       // k index within group

    int node0 = blockIdx.x * 128 + warp * 16;
    int r0 = node0 + grp;
    int r1 = r0 + 8;
    int rr0 = (r0 < N_NODES) ? r0 : (N_NODES - 1);
    int rr1 = (r1 < N_NODES) ? r1 : (N_NODES - 1);

    float d[8][4];
#pragma unroll
    for (int nt = 0; nt < 8; nt++)
#pragma unroll
        for (int j = 0; j < 4; j++) d[nt][j] = 0.f;

    for (int h = 0; h < 2; h++) {
        __syncthreads();
        for (int i = tid; i < 128 * 64; i += 256) {
            int kl = i >> 6;
            int n  = i & 63;
            float w = W1[(h * 128 + kl) * NHID + n];
            float hi = __uint_as_float(f2tf32(w));
            float lo = __uint_as_float(f2tf32(w - hi));
            Wt[n * KP + kl] = make_float2(hi, lo);
        }
        __syncthreads();

        int kg0 = h * 128;
#pragma unroll 4
        for (int ks = 0; ks < 16; ks++) {
            int kc = kg0 + ks * 8 + tig;
            float a0 = __ldg(&x[rr0 * NFEAT + kc]);
            float a1 = __ldg(&x[rr1 * NFEAT + kc]);
            float a2 = __ldg(&x[rr0 * NFEAT + kc + 4]);
            float a3 = __ldg(&x[rr1 * NFEAT + kc + 4]);
            uint32_t ah[4], al[4];
            ah[0] = f2tf32(a0); al[0] = f2tf32(a0 - __uint_as_float(ah[0]));
            ah[1] = f2tf32(a1); al[1] = f2tf32(a1 - __uint_as_float(ah[1]));
            ah[2] = f2tf32(a2); al[2] = f2tf32(a2 - __uint_as_float(ah[2]));
            ah[3] = f2tf32(a3); al[3] = f2tf32(a3 - __uint_as_float(ah[3]));

            int kb = ks * 8 + tig;
#pragma unroll
            for (int nt = 0; nt < 8; nt++) {
                float2 p0 = Wt[(nt * 8 + grp) * KP + kb];
                float2 p1 = Wt[(nt * 8 + grp) * KP + kb + 4];
                uint32_t b0h = __float_as_uint(p0.x), b0l = __float_as_uint(p0.y);
                uint32_t b1h = __float_as_uint(p1.x), b1l = __float_as_uint(p1.y);
                mma_tf32(d[nt], ah, b0h, b1h);
                mma_tf32(d[nt], ah, b0l, b1l);
                mma_tf32(d[nt], al, b0h, b1h);
            }
        }
    }

#pragma unroll
    for (int nt = 0; nt < 8; nt++) {
        int c = nt * 8 + 2 * tig;
        if (r0 < N_NODES)
            *(float2*)(g_A + r0 * NHID + c) = make_float2(d[nt][0], d[nt][1]);
        if (r1 < N_NODES)
            *(float2*)(g_A + r1 * NHID + c) = make_float2(d[nt][2], d[nt][3]);
    }
}

// ---------------------------------------------------------------------------
// SpMM1: g_hacc[dst] += g_A[src] * w.  PDL: meta loads before grid-dep sync.
// ---------------------------------------------------------------------------
__global__ void spmm1_kernel(const float* __restrict__ ew,
                             const int* __restrict__ esrc,
                             const int* __restrict__ edst) {
    int gid = blockIdx.x * blockDim.x + threadIdx.x;
    int e = gid >> 4;
    int q = gid & 15;
    int ee = (e < N_EDGES) ? e : (N_EDGES - 1);

    // Independent prologue: edge metadata (inputs, not produced by gemm1)
    int s = __ldg(&esrc[ee]);
    int d = __ldg(&edst[ee]);
    float w = __ldg(&ew[ee]);

    // Wait for gemm1 (g_A written, g_hacc zeroed)
    cudaGridDependencySynchronize();

    if (e >= N_EDGES) return;
    float4 a = ((const float4*)g_A)[s * 16 + q];
    float4 m = make_float4(a.x * w, a.y * w, a.z * w, a.w * w);
    atomicAdd((float4*)&g_hacc[d * NHID + q * 4], m);
}

// ---------------------------------------------------------------------------
// Layer2 via mma.sync tf32 (3-pass): g_B = relu(g_hacc + b1) @ W2.
// PDL: W2/b1 smem staging before grid-dep sync.
// ---------------------------------------------------------------------------
#define KP2 68
__global__ __launch_bounds__(256) void layer2_tc_kernel(const float* __restrict__ b1,
                                                        const float* __restrict__ W2) {
    __shared__ float2 W2t[NCLASS * KP2]; // 40*68*8 = 21760 B
    __shared__ float b1s[NHID];

    int tid = threadIdx.x;
    // Independent prologue: stage weights (inputs, not produced by spmm1)
    for (int i = tid; i < NHID * NCLASS; i += 256) {
        int k = i / NCLASS, n = i - k * NCLASS;
        float w = W2[i];
        float hi = __uint_as_float(f2tf32(w));
        float lo = __uint_as_float(f2tf32(w - hi));
        W2t[n * KP2 + k] = make_float2(hi, lo);
    }
    if (tid < NHID) b1s[tid] = b1[tid];
    __syncthreads();

    // Wait for spmm1 (g_hacc complete)
    cudaGridDependencySynchronize();

    int warp = tid >> 5, lane = tid & 31;
    int grp = lane >> 2, tig = lane & 3;

    int node0 = blockIdx.x * 128 + warp * 16;
    int r0 = node0 + grp;
    int r1 = r0 + 8;
    int rr0 = (r0 < N_NODES) ? r0 : (N_NODES - 1);
    int rr1 = (r1 < N_NODES) ? r1 : (N_NODES - 1);

    float d[5][4];
#pragma unroll
    for (int nt = 0; nt < 5; nt++)
#pragma unroll
        for (int j = 0; j < 4; j++) d[nt][j] = 0.f;

#pragma unroll
    for (int ks = 0; ks < 8; ks++) {
        int kc = ks * 8 + tig;
        float a0 = fmaxf(g_hacc[rr0 * NHID + kc]     + b1s[kc],     0.f);
        float a1 = fmaxf(g_hacc[rr1 * NHID + kc]     + b1s[kc],     0.f);
        float a2 = fmaxf(g_hacc[rr0 * NHID + kc + 4] + b1s[kc + 4], 0.f);
        float a3 = fmaxf(g_hacc[rr1 * NHID + kc + 4] + b1s[kc + 4], 0.f);
        uint32_t ah[4], al[4];
        ah[0] = f2tf32(a0); al[0] = f2tf32(a0 - __uint_as_float(ah[0]));
        ah[1] = f2tf32(a1); al[1] = f2tf32(a1 - __uint_as_float(ah[1]));
        ah[2] = f2tf32(a2); al[2] = f2tf32(a2 - __uint_as_float(ah[2]));
        ah[3] = f2tf32(a3); al[3] = f2tf32(a3 - __uint_as_float(ah[3]));

#pragma unroll
        for (int nt = 0; nt < 5; nt++) {
            float2 p0 = W2t[(nt * 8 + grp) * KP2 + kc];
            float2 p1 = W2t[(nt * 8 + grp) * KP2 + kc + 4];
            uint32_t b0h = __float_as_uint(p0.x), b0l = __float_as_uint(p0.y);
            uint32_t b1h = __float_as_uint(p1.x), b1l = __float_as_uint(p1.y);
            mma_tf32(d[nt], ah, b0h, b1h);
            mma_tf32(d[nt], ah, b0l, b1l);
            mma_tf32(d[nt], al, b0h, b1h);
        }
    }

#pragma unroll
    for (int nt = 0; nt < 5; nt++) {
        int c = nt * 8 + 2 * tig;
        if (r0 < N_NODES)
            *(float2*)(g_B + r0 * NCLASS + c) = make_float2(d[nt][0], d[nt][1]);
        if (r1 < N_NODES)
            *(float2*)(g_B + r1 * NCLASS + c) = make_float2(d[nt][2], d[nt][3]);
    }
}

// ---------------------------------------------------------------------------
// SpMM2: g_lacc[dst] += g_B[src] * w.  PDL: meta loads before grid-dep sync.
// ---------------------------------------------------------------------------
__global__ void spmm2_kernel(const float* __restrict__ ew,
                             const int* __restrict__ esrc,
                             const int* __restrict__ edst) {
    int gid = blockIdx.x * blockDim.x + threadIdx.x;
    int e = gid / 10;
    int q = gid - e * 10;
    int ee = (e < N_EDGES) ? e : (N_EDGES - 1);

    int s = __ldg(&esrc[ee]);
    int d = __ldg(&edst[ee]);
    float w = __ldg(&ew[ee]);

    cudaGridDependencySynchronize();

    if (e >= N_EDGES) return;
    float4 a = ((const float4*)g_B)[s * 10 + q];
    float4 m = make_float4(a.x * w, a.y * w, a.z * w, a.w * w);
    atomicAdd((float4*)&g_lacc[d * NCLASS + q * 4], m);
}

// ---------------------------------------------------------------------------
// Finalize: logits = g_lacc + b2; out[0:2M]=logits, out[2M:4M]=log_softmax
// PDL: b2 staging before grid-dep sync.
// ---------------------------------------------------------------------------
__global__ __launch_bounds__(128) void finalize_kernel(const float* __restrict__ b2,
                                                       float* __restrict__ out) {
    __shared__ float b2s[NCLASS];
    if (threadIdx.x < NCLASS) b2s[threadIdx.x] = b2[threadIdx.x];
    __syncthreads();

    cudaGridDependencySynchronize();

    int node = blockIdx.x * 128 + threadIdx.x;
    if (node >= N_NODES) return;

    float v[NCLASS];
    float mx = -INFINITY;
    const float4* lin = (const float4*)(g_lacc + node * NCLASS);
#pragma unroll
    for (int jj = 0; jj < 10; jj++) {
        float4 a = lin[jj];
        v[jj * 4 + 0] = a.x + b2s[jj * 4 + 0];
        v[jj * 4 + 1] = a.y + b2s[jj * 4 + 1];
        v[jj * 4 + 2] = a.z + b2s[jj * 4 + 2];
        v[jj * 4 + 3] = a.w + b2s[jj * 4 + 3];
    }
#pragma unroll
    for (int j = 0; j < NCLASS; j++) mx = fmaxf(mx, v[j]);
    float s = 0.f;
#pragma unroll
    for (int j = 0; j < NCLASS; j++) s += expf(v[j] - mx);
    float lse = mx + logf(s);

    float4* o1 = (float4*)(out + node * NCLASS);
    float4* o2 = (float4*)(out + LOGSM_OFF + node * NCLASS);
#pragma unroll
    for (int jj = 0; jj < 10; jj++) {
        float4 a = make_float4(v[jj * 4 + 0], v[jj * 4 + 1],
                               v[jj * 4 + 2], v[jj * 4 + 3]);
        o1[jj] = a;
        float4 b = make_float4(a.x - lse, a.y - lse, a.z - lse, a.w - lse);
        o2[jj] = b;
    }
}

// ---------------------------------------------------------------------------
// PDL launch helper: consumer may launch early; kernel gates on
// cudaGridDependencySynchronize() before touching producer data.
// ---------------------------------------------------------------------------
template <typename F, typename... Args>
static void launch_pdl(F* fn, dim3 grid, dim3 block, size_t smem, Args... args) {
    cudaLaunchConfig_t cfg = {};
    cfg.gridDim = grid;
    cfg.blockDim = block;
    cfg.dynamicSmemBytes = smem;
    cfg.stream = 0; // legacy default stream (same as <<<>>> used before)
    cudaLaunchAttribute attr[1];
    attr[0].id = cudaLaunchAttributeProgrammaticStreamSerialization;
    attr[0].val.programmaticStreamSerializationAllowed = 1;
    cfg.attrs = attr;
    cfg.numAttrs = 1;
    cudaLaunchKernelEx(&cfg, fn, args...);
}

// ---------------------------------------------------------------------------
extern "C" void kernel_launch(void* const* d_in, const int* in_sizes, int n_in,
                              void* d_out, int out_size) {
    const float* x   = (const float*)d_in[0];
    const float* W1  = (const float*)d_in[1];
    const float* b1  = (const float*)d_in[2];
    const float* W2  = (const float*)d_in[3];
    const float* b2  = (const float*)d_in[4];
    const float* ew  = (const float*)d_in[5];
    const int*  esrc = (const int*)d_in[6];
    const int*  edst = (const int*)d_in[7];
    float* out = (float*)d_out;

    cudaFuncSetAttribute(gemm1_tc_kernel,
                         cudaFuncAttributeMaxDynamicSharedMemorySize, G1_SMEM);

    // GEMM1 (3-pass tf32) + fused accumulator zeroing — head of the chain
    {
        int nblk = (N_NODES + 127) / 128; // 391
        gemm1_tc_kernel<<<nblk, 256, G1_SMEM>>>(x, W1);
    }
    // SpMM1 — PDL overlap of meta prologue with gemm1 tail
    {
        int total = N_EDGES * 16; // 12.8M
        launch_pdl(spmm1_kernel, dim3((total + 255) / 256), dim3(256), 0,
                   ew, esrc, edst);
    }
    // Layer2 — PDL overlap of W2/b1 smem staging with spmm1 tail
    {
        int nblk = (N_NODES + 127) / 128; // 391
        launch_pdl(layer2_tc_kernel, dim3(nblk), dim3(256), 0, b1, W2);
    }
    // SpMM2 — PDL overlap of meta prologue with layer2 tail
    {
        int total = N_EDGES * 10; // 8M
        launch_pdl(spmm2_kernel, dim3((total + 255) / 256), dim3(256), 0,
                   ew, esrc, edst);
    }
    // Finalize — PDL overlap of b2 staging with spmm2 tail
    launch_pdl(finalize_kernel, dim3((N_NODES + 127) / 128), dim3(128), 0,
               b2, out);
}